// round 2
// baseline (speedup 1.0000x reference)
#include <cuda_runtime.h>
#include <math.h>

#define BATCH 16
#define DIM   48
#define HID   16
#define CH    8
#define IMG   256
#define HW    (IMG*IMG)
#define ROWS  (BATCH*HW)

// Scratch (allocation rules: __device__ globals are allowed)
__device__ float g_x1[(size_t)ROWS * CH];   // 33.5 MB
__device__ float g_n [(size_t)ROWS * CH];   // 33.5 MB

// ---------------------------------------------------------------------------
// K1: t = gelu(gelu(x @ W1 + b1)); x1 = t[:, :8]; n = LN(t[:, 8:16])
// One thread per pixel-row (48 contiguous floats of x).
// ---------------------------------------------------------------------------
__global__ __launch_bounds__(256) void k1_gemm_gelu_ln(
    const float* __restrict__ x, const float* __restrict__ W1,
    const float* __restrict__ b1, const float* __restrict__ gamma,
    const float* __restrict__ beta)
{
    __shared__ float sW1[DIM * HID];
    __shared__ float sb1[HID];
    __shared__ float sg[CH], sb[CH];

    int tid = threadIdx.x;
    for (int i = tid; i < DIM * HID; i += blockDim.x) sW1[i] = W1[i];
    if (tid < HID) sb1[tid] = b1[tid];
    if (tid < CH)  { sg[tid] = gamma[tid]; sb[tid] = beta[tid]; }
    __syncthreads();

    int r = blockIdx.x * blockDim.x + tid;   // ROWS is a multiple of 256
    const float4* xr = (const float4*)(x + (size_t)r * DIM);

    float z[HID];
    #pragma unroll
    for (int j = 0; j < HID; j++) z[j] = sb1[j];

    #pragma unroll
    for (int k4 = 0; k4 < DIM / 4; k4++) {
        float4 v = xr[k4];
        float xs[4] = {v.x, v.y, v.z, v.w};
        #pragma unroll
        for (int kk = 0; kk < 4; kk++) {
            float xv = xs[kk];
            const float* wrow = &sW1[(k4 * 4 + kk) * HID];
            #pragma unroll
            for (int j = 0; j < HID; j++) z[j] += xv * wrow[j];
        }
    }

    // Exact GELU applied twice: gelu(v) = 0.5 v (1 + erf(v/sqrt(2)))
    const float kInvSqrt2 = 0.70710678118654752440f;
    #pragma unroll
    for (int j = 0; j < HID; j++) {
        float v = z[j];
        v = 0.5f * v * (1.0f + erff(v * kInvSqrt2));
        v = 0.5f * v * (1.0f + erff(v * kInvSqrt2));
        z[j] = v;
    }

    // x1 = z[0:8]
    float4* o1 = (float4*)(g_x1 + (size_t)r * CH);
    o1[0] = make_float4(z[0], z[1], z[2], z[3]);
    o1[1] = make_float4(z[4], z[5], z[6], z[7]);

    // LayerNorm over z[8:16]
    float m = 0.0f;
    #pragma unroll
    for (int j = 8; j < 16; j++) m += z[j];
    m *= 0.125f;
    float var = 0.0f;
    #pragma unroll
    for (int j = 8; j < 16; j++) { float d = z[j] - m; var += d * d; }
    var *= 0.125f;
    float inv = rsqrtf(var + 1e-5f);

    float nn[CH];
    #pragma unroll
    for (int j = 0; j < CH; j++) nn[j] = (z[8 + j] - m) * inv * sg[j] + sb[j];

    float4* o2 = (float4*)(g_n + (size_t)r * CH);
    o2[0] = make_float4(nn[0], nn[1], nn[2], nn[3]);
    o2[1] = make_float4(nn[4], nn[5], nn[6], nn[7]);
}

// ---------------------------------------------------------------------------
// K2: dw3x3 + pw1x1 on n, gate with x1, GEMM(8->48), transposed store.
// Block = 32x8 spatial tile; smem tile of n with 1-pixel halo.
// Channel stride padded to 9 floats -> conflict-free LDS (gcd(9,32)=1).
// ---------------------------------------------------------------------------
#define TX 32
#define TY 8
#define HALO_W (TX + 2)
#define HALO_H (TY + 2)
#define NPAD 9

__global__ __launch_bounds__(TX * TY) void k2_conv_gate_gemm(
    const float* __restrict__ dw_w, const float* __restrict__ dw_b,
    const float* __restrict__ pw_w, const float* __restrict__ pw_b,
    const float* __restrict__ W2,   const float* __restrict__ b2,
    float* __restrict__ out)
{
    __shared__ float sn[HALO_H][HALO_W][NPAD];
    __shared__ float sdw[CH * 9], sdwb[CH];
    __shared__ float spw[CH * CH], spwb[CH];
    __shared__ float sW2[CH * DIM], sb2[DIM];

    int tid = threadIdx.y * TX + threadIdx.x;

    if (tid < CH * 9)               sdw[tid]        = dw_w[tid];
    if (tid >= 96  && tid < 104)    sdwb[tid - 96]  = dw_b[tid - 96];
    if (tid >= 104 && tid < 168)    spw[tid - 104]  = pw_w[tid - 104];
    if (tid >= 168 && tid < 176)    spwb[tid - 168] = pw_b[tid - 168];
    if (tid >= 176 && tid < 224)    sb2[tid - 176]  = b2[tid - 176];
    for (int i = tid; i < CH * DIM; i += TX * TY) sW2[i] = W2[i];

    int b   = blockIdx.z;
    int tx0 = blockIdx.x * TX;
    int ty0 = blockIdx.y * TY;
    const float* nb = g_n + (size_t)b * HW * CH;

    // Cooperative halo load (zero-pad at image borders = SAME padding)
    for (int i = tid; i < HALO_H * HALO_W; i += TX * TY) {
        int hy = i / HALO_W, hx = i % HALO_W;
        int gy = ty0 + hy - 1, gx = tx0 + hx - 1;
        float4 a = make_float4(0.f, 0.f, 0.f, 0.f);
        float4 c = make_float4(0.f, 0.f, 0.f, 0.f);
        if (gy >= 0 && gy < IMG && gx >= 0 && gx < IMG) {
            const float4* src = (const float4*)(nb + ((size_t)gy * IMG + gx) * CH);
            a = src[0]; c = src[1];
        }
        float* dst = &sn[hy][hx][0];
        dst[0] = a.x; dst[1] = a.y; dst[2] = a.z; dst[3] = a.w;
        dst[4] = c.x; dst[5] = c.y; dst[6] = c.z; dst[7] = c.w;
    }
    __syncthreads();

    int lx = threadIdx.x + 1, ly = threadIdx.y + 1;

    float ncen[CH];
    #pragma unroll
    for (int c = 0; c < CH; c++) ncen[c] = sn[ly][lx][c];

    // Depthwise 3x3 (cross-correlation)
    float sp[CH];
    #pragma unroll
    for (int c = 0; c < CH; c++) sp[c] = sdwb[c];
    #pragma unroll
    for (int dy = 0; dy < 3; dy++) {
        #pragma unroll
        for (int dx = 0; dx < 3; dx++) {
            #pragma unroll
            for (int c = 0; c < CH; c++)
                sp[c] += sn[ly + dy - 1][lx + dx - 1][c] * sdw[c * 9 + dy * 3 + dx];
        }
    }

    // Pointwise 1x1 (8 -> 8)
    float chv[CH];
    #pragma unroll
    for (int c = 0; c < CH; c++) {
        float acc = spwb[c];
        #pragma unroll
        for (int i = 0; i < CH; i++) acc += ncen[i] * spw[c * CH + i];
        chv[c] = acc;
    }

    // Gate with x1
    int p = (ty0 + threadIdx.y) * IMG + (tx0 + threadIdx.x);
    const float4* x1p = (const float4*)(g_x1 + ((size_t)b * HW + p) * CH);
    float4 xa = x1p[0], xb = x1p[1];
    float g[CH] = {xa.x, xa.y, xa.z, xa.w, xb.x, xb.y, xb.z, xb.w};
    #pragma unroll
    for (int c = 0; c < CH; c++) g[c] *= sp[c] * chv[c];

    // GEMM 8 -> 48, transposed (d-major) coalesced store
    float* ob = out + (size_t)b * DIM * HW + p;
    #pragma unroll
    for (int d = 0; d < DIM; d++) {
        float acc = sb2[d];
        #pragma unroll
        for (int c = 0; c < CH; c++) acc += g[c] * sW2[c * DIM + d];
        ob[(size_t)d * HW] = acc;
    }
}

// ---------------------------------------------------------------------------
extern "C" void kernel_launch(void* const* d_in, const int* in_sizes, int n_in,
                              void* d_out, int out_size)
{
    const float* x     = (const float*)d_in[0];
    const float* W1    = (const float*)d_in[1];
    const float* b1    = (const float*)d_in[2];
    const float* gamma = (const float*)d_in[3];
    const float* beta  = (const float*)d_in[4];
    const float* dw_w  = (const float*)d_in[5];
    const float* dw_b  = (const float*)d_in[6];
    const float* pw_w  = (const float*)d_in[7];
    const float* pw_b  = (const float*)d_in[8];
    const float* W2    = (const float*)d_in[9];
    const float* b2    = (const float*)d_in[10];
    float* out = (float*)d_out;

    k1_gemm_gelu_ln<<<ROWS / 256, 256>>>(x, W1, b1, gamma, beta);

    dim3 g2(IMG / TX, IMG / TY, BATCH);
    k2_conv_gate_gemm<<<g2, dim3(TX, TY)>>>(dw_w, dw_b, pw_w, pw_b, W2, b2, out);
}